// round 11
// baseline (speedup 1.0000x reference)
#include <cuda_runtime.h>
#include <cstdint>

#define MTOK 8192
#define DDIM 4096
#define ODIM 4096
#define NEXP 8
#define RRNK 16
#define ERD  128
#define NLOG 15
#define SCALING 2.0f

// conflict-free smem unit permutation: adjacent rows differ in bit 2
#define PERM(r) ((((r) & 1) << 2) | (((r) >> 1) & 3))

// Scratch (allocation-free rule: __device__ globals)
__device__ float g_w[MTOK * NEXP];       // per-token expert combine weights
__device__ float g_hw[MTOK * ERD];       // w-scaled low-rank acts (tf32-rounded)
__device__ float g_BcatT[ODIM * ERD];    // B transposed [o][er] (tf32-rounded)
__device__ float g_xr[MTOK * DDIM];      // x pre-rounded to tf32
__device__ float g_wr[ODIM * DDIM];      // base_W pre-rounded to tf32
__device__ float g_ar[ERD * DDIM];       // A_flat tf32
__device__ float g_h[MTOK * 192];        // cols 0..127: h, 128..142: fp32 logits

typedef unsigned long long u64;

__device__ __forceinline__ u64 pack2(float lo, float hi) {
    u64 r; asm("mov.b64 %0, {%1,%2};" : "=l"(r) : "f"(lo), "f"(hi)); return r;
}
__device__ __forceinline__ void unpack2(u64 v, float& lo, float& hi) {
    asm("mov.b64 {%0,%1}, %2;" : "=f"(lo), "=f"(hi) : "l"(v));
}
__device__ __forceinline__ void fma2(u64& d, u64 a, u64 b) {
    asm("fma.rn.f32x2 %0, %1, %2, %0;" : "+l"(d) : "l"(a), "l"(b));
}
__device__ __forceinline__ uint32_t tf32r(float f) {
    uint32_t r; asm("cvt.rna.tf32.f32 %0, %1;" : "=r"(r) : "f"(f)); return r;
}
__device__ __forceinline__ uint32_t smem_u32(const void* p) {
    uint32_t a;
    asm("{ .reg .u64 t; cvta.to.shared.u64 t, %1; cvt.u32.u64 %0, t; }" : "=r"(a) : "l"(p));
    return a;
}
__device__ __forceinline__ void cpasync16(uint32_t saddr, const void* g) {
    asm volatile("cp.async.cg.shared.global [%0], [%1], 16;" :: "r"(saddr), "l"(g));
}
__device__ __forceinline__ void mma_tf32(float* d, uint32_t a0, uint32_t a1,
                                         uint32_t a2, uint32_t a3,
                                         uint32_t b0, uint32_t b1) {
    asm("mma.sync.aligned.m16n8k8.row.col.f32.tf32.tf32.f32 "
        "{%0,%1,%2,%3}, {%4,%5,%6,%7}, {%8,%9}, {%0,%1,%2,%3};"
        : "+f"(d[0]), "+f"(d[1]), "+f"(d[2]), "+f"(d[3])
        : "r"(a0), "r"(a1), "r"(a2), "r"(a3), "r"(b0), "r"(b1));
}

// ---------------------------------------------------------------------------
// Pre-rounding kernels
// ---------------------------------------------------------------------------
__global__ void round_x_kernel(const float* __restrict__ src) {
    int i = blockIdx.x * blockDim.x + threadIdx.x;
    float4 v = ((const float4*)src)[i];
    ((uint4*)g_xr)[i] = make_uint4(tf32r(v.x), tf32r(v.y), tf32r(v.z), tf32r(v.w));
}
__global__ void round_w_kernel(const float* __restrict__ src) {
    int i = blockIdx.x * blockDim.x + threadIdx.x;
    float4 v = ((const float4*)src)[i];
    ((uint4*)g_wr)[i] = make_uint4(tf32r(v.x), tf32r(v.y), tf32r(v.z), tf32r(v.w));
}
__global__ void ar_fill_kernel(const float* __restrict__ A) {
    int i = blockIdx.x * blockDim.x + threadIdx.x;
    float4 v = ((const float4*)A)[i];
    ((uint4*)g_ar)[i] = make_uint4(tf32r(v.x), tf32r(v.y), tf32r(v.z), tf32r(v.w));
}
__global__ void bcat_kernel(const float* __restrict__ Bm) {
    int idx = blockIdx.x * blockDim.x + threadIdx.x;
    if (idx < ODIM * ERD) {
        int o  = idx >> 7;
        int er = idx & 127;
        int e = er >> 4, r = er & 15;
        ((uint32_t*)g_BcatT)[idx] = tf32r(Bm[((size_t)e * ODIM + o) * RRNK + r]);
    }
}

// ---------------------------------------------------------------------------
// Exact fp32 router logits
// ---------------------------------------------------------------------------
__global__ __launch_bounds__(256, 1)
void logits_kernel(const float* __restrict__ x, const float* __restrict__ rW) {
    int tid = threadIdx.x;
    int tok = blockIdx.x * 64 + (tid >> 2);
    int part = tid & 3;
    u64 acc[NLOG];
#pragma unroll
    for (int n = 0; n < NLOG; n++) acc[n] = 0;
    const float4* xr = (const float4*)(x + (size_t)tok * DDIM);
    for (int k4 = part; k4 < DDIM / 4; k4 += 4) {
        float4 xv = xr[k4];
        u64 xp0 = pack2(xv.x, xv.y), xp1 = pack2(xv.z, xv.w);
#pragma unroll
        for (int n = 0; n < NLOG; n++) {
            float4 wv = ((const float4*)(rW + (size_t)n * DDIM))[k4];
            fma2(acc[n], xp0, pack2(wv.x, wv.y));
            fma2(acc[n], xp1, pack2(wv.z, wv.w));
        }
    }
    __shared__ float red[4][64][NLOG + 1];
#pragma unroll
    for (int n = 0; n < NLOG; n++) {
        float lo, hi; unpack2(acc[n], lo, hi);
        red[part][tid >> 2][n] = lo + hi;
    }
    __syncthreads();
    if (part == 0) {
        int tl = tid >> 2;
#pragma unroll
        for (int n = 0; n < NLOG; n++)
            g_h[(size_t)tok * 192 + ERD + n] =
                red[0][tl][n] + red[1][tl][n] + red[2][tl][n] + red[3][tl][n];
    }
}

// ---------------------------------------------------------------------------
// h GEMM (tf32 mma):  g_h[:, 0:128] = g_xr @ g_ar^T
// ---------------------------------------------------------------------------
#define BMH 64
#define BNH 128
#define AH_BYTES (BMH * 32 * 4)           // 8192
#define BH_BYTES (BNH * 32 * 4)           // 16384
#define STGH_BYTES (AH_BYTES + BH_BYTES)  // 24576
#define SMEMH_BYTES (3 * STGH_BYTES)      // 73728

__device__ __forceinline__ void hwr_issue(int i, int stg, int m0, int tid,
                                          uint32_t smem_base) {
    int k0 = i * 32;
    uint32_t sa = smem_base + stg * STGH_BYTES;
    uint32_t sb = sa + AH_BYTES;
#pragma unroll
    for (int j = 0; j < 2; j++) {
        int g = tid + j * 256, row = g >> 3, u = g & 7;
        cpasync16(sa + row * 128 + ((u ^ PERM(row)) << 4),
                  g_xr + (size_t)(m0 + row) * DDIM + k0 + u * 4);
    }
#pragma unroll
    for (int j = 0; j < 4; j++) {
        int g = tid + j * 256, row = g >> 3, u = g & 7;
        cpasync16(sb + row * 128 + ((u ^ PERM(row)) << 4),
                  g_ar + (size_t)row * DDIM + k0 + u * 4);
    }
}

__global__ __launch_bounds__(256, 1)
void hwr_kernel() {
    extern __shared__ char smem[];
    uint32_t smem_base = smem_u32(smem);
    int tid = threadIdx.x;
    int wid = tid >> 5;
    int lane = tid & 31;
    int wm = wid >> 2;
    int wn = wid & 3;
    int c = lane & 3;
    int rq = lane >> 2;
    int m0 = blockIdx.x * BMH;

    float acc[2][4][4];
#pragma unroll
    for (int i = 0; i < 2; i++)
#pragma unroll
        for (int j = 0; j < 4; j++)
#pragma unroll
            for (int q = 0; q < 4; q++) acc[i][j][q] = 0.f;

    int aoff[2][2], boff[4];
#pragma unroll
    for (int i = 0; i < 2; i++) {
        int r0 = wm * 32 + i * 16 + rq, r1 = r0 + 8;
        aoff[i][0] = r0 * 128 + ((c ^ PERM(r0)) << 4);
        aoff[i][1] = r1 * 128 + ((c ^ PERM(r1)) << 4);
    }
#pragma unroll
    for (int j = 0; j < 4; j++) {
        int n = wn * 32 + j * 8 + rq;
        boff[j] = n * 128 + ((c ^ PERM(n)) << 4);
    }

    hwr_issue(0, 0, m0, tid, smem_base);
    asm volatile("cp.async.commit_group;" ::: "memory");
    hwr_issue(1, 1, m0, tid, smem_base);
    asm volatile("cp.async.commit_group;" ::: "memory");

    const int NCH = DDIM / 32;
    for (int i = 0; i < NCH; i++) {
        asm volatile("cp.async.wait_group 1;" ::: "memory");
        __syncthreads();
        if (i + 2 < NCH) hwr_issue(i + 2, (i + 2) % 3, m0, tid, smem_base);
        asm volatile("cp.async.commit_group;" ::: "memory");

        const char* sa = smem + (i % 3) * STGH_BYTES;
        const char* sb = sa + AH_BYTES;
#pragma unroll
        for (int p = 0; p < 2; p++) {
            uint4 af[2][2], bf[4];
#pragma unroll
            for (int ii = 0; ii < 2; ii++) {
                af[ii][0] = *(const uint4*)(sa + (aoff[ii][0] ^ (p << 6)));
                af[ii][1] = *(const uint4*)(sa + (aoff[ii][1] ^ (p << 6)));
            }
#pragma unroll
            for (int jj = 0; jj < 4; jj++)
                bf[jj] = *(const uint4*)(sb + (boff[jj] ^ (p << 6)));
#pragma unroll
            for (int ii = 0; ii < 2; ii++)
#pragma unroll
                for (int jj = 0; jj < 4; jj++) {
                    mma_tf32(acc[ii][jj],
                             af[ii][0].x, af[ii][1].x, af[ii][0].y, af[ii][1].y,
                             bf[jj].x, bf[jj].y);
                    mma_tf32(acc[ii][jj],
                             af[ii][0].z, af[ii][1].z, af[ii][0].w, af[ii][1].w,
                             bf[jj].z, bf[jj].w);
                }
        }
    }

#pragma unroll
    for (int j = 0; j < 4; j++) {
        int col = wn * 32 + j * 8 + 2 * c;
#pragma unroll
        for (int i = 0; i < 2; i++) {
            int row = m0 + wm * 32 + i * 16 + rq;
            *(float2*)(g_h + (size_t)row * 192 + col) =
                make_float2(acc[i][j][0], acc[i][j][1]);
            *(float2*)(g_h + (size_t)(row + 8) * 192 + col) =
                make_float2(acc[i][j][2], acc[i][j][3]);
        }
    }
}

// ---------------------------------------------------------------------------
// w_kernel + scale_kernel
// ---------------------------------------------------------------------------
__global__ void w_kernel(const float* __restrict__ rb,
                         const int* __restrict__ emap) {
    int t = blockIdx.x * blockDim.x + threadIdx.x;
    if (t >= MTOK) return;
    float p[NLOG];
    float mx = -1e30f;
#pragma unroll
    for (int n = 0; n < NLOG; n++) {
        p[n] = g_h[(size_t)t * 192 + ERD + n] + rb[n];
        mx = fmaxf(mx, p[n]);
    }
    float s = 0.f;
#pragma unroll
    for (int n = 0; n < NLOG; n++) { p[n] = expf(p[n] - mx); s += p[n]; }
    float inv = 1.f / s;
#pragma unroll
    for (int n = 0; n < NLOG; n++) p[n] *= inv;
    float wacc[NEXP];
#pragma unroll
    for (int e = 0; e < NEXP; e++) wacc[e] = 0.f;
    bool used[NLOG];
#pragma unroll
    for (int n = 0; n < NLOG; n++) used[n] = false;
    for (int k = 0; k < NEXP; k++) {
        int best = 0; float bv = -1e30f;
        for (int n = 0; n < NLOG; n++)
            if (!used[n] && p[n] > bv) { bv = p[n]; best = n; }
        used[best] = true;
        wacc[emap[best]] += bv;
    }
#pragma unroll
    for (int e = 0; e < NEXP; e++) g_w[t * NEXP + e] = wacc[e];
}

__global__ void scale_kernel() {
    int idx = blockIdx.x * blockDim.x + threadIdx.x;
    int t = idx >> 5;
    int er4 = (idx & 31) * 4;
    float wv = g_w[t * NEXP + (er4 >> 4)] * SCALING;
    const float* h = g_h + (size_t)t * 192 + er4;
    ((uint4*)(g_hw + (size_t)t * ERD + er4))[0] =
        make_uint4(tf32r(h[0] * wv), tf32r(h[1] * wv),
                   tf32r(h[2] * wv), tf32r(h[3] * wv));
}

// ---------------------------------------------------------------------------
// Main GEMM: tf32 mma.sync, 4-stage cp.async pipeline (R7 shape), with the
// conflict-free PERM swizzle.
//   out = x@W^T (K=4096) + hw@BcatT^T (K=128) + bias
// CTA 128x256, 8 warps (2x4), warp tile 64x64, K-chunk 32.
// ---------------------------------------------------------------------------
#define BM 128
#define BN 256
#define KC 32
#define NCH_BASE (DDIM / KC)             // 128
#define NCHUNK   (NCH_BASE + ERD / KC)   // 132
#define NSTAGE 4
#define A_BYTES (BM * KC * 4)            // 16384
#define B_BYTES (BN * KC * 4)            // 32768
#define STG_BYTES (A_BYTES + B_BYTES)    // 49152
#define SMEM_BYTES (NSTAGE * STG_BYTES)  // 196608

__device__ __forceinline__ void issue_chunk(int i, int stg, int m0, int n0,
                                            int tid, uint32_t smem_base) {
    const float* as; const float* bs; int lda, ldb;
    if (i < NCH_BASE) {
        int k0 = i * KC; as = g_xr + k0; lda = DDIM; bs = g_wr + k0; ldb = DDIM;
    } else {
        int k0 = (i - NCH_BASE) * KC; as = g_hw + k0; lda = ERD; bs = g_BcatT + k0; ldb = ERD;
    }
    uint32_t sa = smem_base + stg * STG_BYTES;
    uint32_t sb = sa + A_BYTES;
#pragma unroll
    for (int j = 0; j < 4; j++) {
        int g = tid + j * 256, row = g >> 3, u = g & 7;
        cpasync16(sa + row * 128 + ((u ^ PERM(row)) << 4),
                  as + (size_t)(m0 + row) * lda + u * 4);
    }
#pragma unroll
    for (int j = 0; j < 8; j++) {
        int g = tid + j * 256, row = g >> 3, u = g & 7;
        cpasync16(sb + row * 128 + ((u ^ PERM(row)) << 4),
                  bs + (size_t)(n0 + row) * ldb + u * 4);
    }
}

__global__ __launch_bounds__(256, 1)
void main_kernel(const float* __restrict__ bias, float* __restrict__ out) {
    extern __shared__ char smem[];
    uint32_t smem_base = smem_u32(smem);
    int tid = threadIdx.x;
    int wid = tid >> 5;
    int lane = tid & 31;
    int wm = wid >> 2;          // 0..1 -> rows wm*64
    int wn = wid & 3;           // 0..3 -> cols wn*64
    int c = lane & 3;
    int rq = lane >> 2;
    int m0 = blockIdx.y * BM;
    int n0 = blockIdx.x * BN;

    float acc[4][8][4];
#pragma unroll
    for (int i = 0; i < 4; i++)
#pragma unroll
        for (int j = 0; j < 8; j++)
#pragma unroll
            for (int q = 0; q < 4; q++) acc[i][j][q] = 0.f;

    int aoff[4][2], boff[8];
#pragma unroll
    for (int i = 0; i < 4; i++) {
        int r0 = wm * 64 + i * 16 + rq, r1 = r0 + 8;
        aoff[i][0] = r0 * 128 + ((c ^ PERM(r0)) << 4);
        aoff[i][1] = r1 * 128 + ((c ^ PERM(r1)) << 4);
    }
#pragma unroll
    for (int j = 0; j < 8; j++) {
        int n = wn * 64 + j * 8 + rq;
        boff[j] = n * 128 + ((c ^ PERM(n)) << 4);
    }

#pragma unroll
    for (int s = 0; s < NSTAGE - 1; s++) {
        issue_chunk(s, s, m0, n0, tid, smem_base);
        asm volatile("cp.async.commit_group;" ::: "memory");
    }

    for (int i = 0; i < NCHUNK; i++) {
        asm volatile("cp.async.wait_group %0;" :: "n"(NSTAGE - 2) : "memory");
        __syncthreads();
        if (i + NSTAGE - 1 < NCHUNK)
            issue_chunk(i + NSTAGE - 1, (i + NSTAGE - 1) % NSTAGE, m0, n0, tid, smem_base);
        asm volatile("cp.async.commit_group;" ::: "memory");

        const char* sa = smem + (i % NSTAGE) * STG_BYTES;
        const char* sb = sa + A_BYTES;
#pragma unroll
        for (int p = 0; p < 2; p++) {
            uint4 af[4][2], bf[8];
#pragma unroll
            for (int ii = 0; ii < 4; ii++) {
                af[ii][0] = *(const uint4*)(sa + (aoff[ii][0] ^ (p << 6)));
                af[ii][1] = *(const uint4*)(sa + (aoff[ii][1] ^ (p << 6)));
            }
#pragma unroll
            for (int jj = 0; jj < 8; jj++)
                bf[jj] = *(const uint4*)(sb + (boff[jj] ^ (p << 6)));
#pragma unroll
            for (int ii = 0; ii < 4; ii++)
#pragma unroll
                for (int jj = 0; jj < 8; jj++) {
                    mma_tf32(acc[ii][jj],
                             af[ii][0].x, af[ii][1].x, af[ii][0].y, af[ii][1].y,
                             bf[jj].x, bf[jj].y);
                    mma_tf32(acc[ii][jj],
                             af[ii][0].z, af[ii][1].z, af[ii][0].w, af[ii][1].w,
                             bf[jj].z, bf[jj].w);
                }
        }
    }

#pragma unroll
    for (int j = 0; j < 8; j++) {
        int col = n0 + wn * 64 + j * 8 + 2 * c;
        float2 bb = *(const float2*)(bias + col);
#pragma unroll
        for (int i = 0; i < 4; i++) {
            int row = m0 + wm * 64 + i * 16 + rq;
            float2 lo = make_float2(acc[i][j][0] + bb.x, acc[i][j][1] + bb.y);
            float2 hi = make_float2(acc[i][j][2] + bb.x, acc[i][j][3] + bb.y);
            *(float2*)(out + (size_t)row * ODIM + col) = lo;
            *(float2*)(out + (size_t)(row + 8) * ODIM + col) = hi;
        }
    }
}

extern "C" void kernel_launch(void* const* d_in, const int* in_sizes, int n_in,
                              void* d_out, int out_size) {
    const float* x    = (const float*)d_in[0];
    const float* bW   = (const float*)d_in[1];
    const float* bb   = (const float*)d_in[2];
    const float* rW   = (const float*)d_in[3];
    const float* rb   = (const float*)d_in[4];
    const float* A    = (const float*)d_in[5];
    const float* Bm   = (const float*)d_in[6];
    const int*   emap = (const int*)d_in[7];
    float* out = (float*)d_out;

    static int configured = 0;
    if (!configured) {
        cudaFuncSetAttribute(main_kernel, cudaFuncAttributeMaxDynamicSharedMemorySize,
                             SMEM_BYTES);
        cudaFuncSetAttribute(hwr_kernel, cudaFuncAttributeMaxDynamicSharedMemorySize,
                             SMEMH_BYTES);
        configured = 1;
    }

    round_x_kernel<<<(MTOK * DDIM / 4) / 256, 256>>>(x);
    round_w_kernel<<<(ODIM * DDIM / 4) / 256, 256>>>(bW);
    ar_fill_kernel<<<(ERD * DDIM / 4) / 256, 256>>>(A);
    bcat_kernel<<<(ODIM * ERD + 255) / 256, 256>>>(Bm);
    logits_kernel<<<MTOK / 64, 256>>>(x, rW);
    hwr_kernel<<<MTOK / BMH, 256, SMEMH_BYTES>>>();
    w_kernel<<<MTOK / 256, 256>>>(rb, emap);
    scale_kernel<<<(MTOK * ERD / 4) / 256, 256>>>();
    dim3 grid(ODIM / BN, MTOK / BM);
    main_kernel<<<grid, 256, SMEM_BYTES>>>(bb, out);
}

// round 12
// speedup vs baseline: 1.0376x; 1.0376x over previous
#include <cuda_runtime.h>
#include <cstdint>

#define MTOK 8192
#define DDIM 4096
#define ODIM 4096
#define NEXP 8
#define RRNK 16
#define ERD  128
#define NLOG 15
#define SCALING 2.0f

// conflict-free smem unit permutation: adjacent rows differ in bit 2
#define PERM(r) ((((r) & 1) << 2) | (((r) >> 1) & 3))

// Scratch (allocation-free rule: __device__ globals)
__device__ float g_w[MTOK * NEXP];       // per-token expert combine weights
__device__ float g_hw[MTOK * ERD];       // w-scaled low-rank acts (tf32-rounded)
__device__ float g_BcatT[ODIM * ERD];    // B transposed [o][er] (tf32-rounded)
__device__ float g_xr[MTOK * DDIM];      // x pre-rounded to tf32
__device__ float g_wr[ODIM * DDIM];      // base_W pre-rounded to tf32
__device__ float g_ar[ERD * DDIM];       // A_flat tf32
__device__ float g_h[MTOK * 192];        // cols 0..127: h, 128..142: fp32 logits

typedef unsigned long long u64;

__device__ __forceinline__ u64 pack2(float lo, float hi) {
    u64 r; asm("mov.b64 %0, {%1,%2};" : "=l"(r) : "f"(lo), "f"(hi)); return r;
}
__device__ __forceinline__ void unpack2(u64 v, float& lo, float& hi) {
    asm("mov.b64 {%0,%1}, %2;" : "=f"(lo), "=f"(hi) : "l"(v));
}
__device__ __forceinline__ void fma2(u64& d, u64 a, u64 b) {
    asm("fma.rn.f32x2 %0, %1, %2, %0;" : "+l"(d) : "l"(a), "l"(b));
}
__device__ __forceinline__ uint32_t tf32r(float f) {
    uint32_t r; asm("cvt.rna.tf32.f32 %0, %1;" : "=r"(r) : "f"(f)); return r;
}
__device__ __forceinline__ uint32_t smem_u32(const void* p) {
    uint32_t a;
    asm("{ .reg .u64 t; cvta.to.shared.u64 t, %1; cvt.u32.u64 %0, t; }" : "=r"(a) : "l"(p));
    return a;
}
__device__ __forceinline__ void cpasync16(uint32_t saddr, const void* g) {
    asm volatile("cp.async.cg.shared.global [%0], [%1], 16;" :: "r"(saddr), "l"(g));
}
__device__ __forceinline__ void mma_tf32(float* d, uint32_t a0, uint32_t a1,
                                         uint32_t a2, uint32_t a3,
                                         uint32_t b0, uint32_t b1) {
    asm("mma.sync.aligned.m16n8k8.row.col.f32.tf32.tf32.f32 "
        "{%0,%1,%2,%3}, {%4,%5,%6,%7}, {%8,%9}, {%0,%1,%2,%3};"
        : "+f"(d[0]), "+f"(d[1]), "+f"(d[2]), "+f"(d[3])
        : "r"(a0), "r"(a1), "r"(a2), "r"(a3), "r"(b0), "r"(b1));
}

// ---------------------------------------------------------------------------
// Pre-rounding kernels
// ---------------------------------------------------------------------------
__global__ void round_x_kernel(const float* __restrict__ src) {
    int i = blockIdx.x * blockDim.x + threadIdx.x;
    float4 v = ((const float4*)src)[i];
    ((uint4*)g_xr)[i] = make_uint4(tf32r(v.x), tf32r(v.y), tf32r(v.z), tf32r(v.w));
}
__global__ void round_w_kernel(const float* __restrict__ src) {
    int i = blockIdx.x * blockDim.x + threadIdx.x;
    float4 v = ((const float4*)src)[i];
    ((uint4*)g_wr)[i] = make_uint4(tf32r(v.x), tf32r(v.y), tf32r(v.z), tf32r(v.w));
}
__global__ void ar_fill_kernel(const float* __restrict__ A) {
    int i = blockIdx.x * blockDim.x + threadIdx.x;
    float4 v = ((const float4*)A)[i];
    ((uint4*)g_ar)[i] = make_uint4(tf32r(v.x), tf32r(v.y), tf32r(v.z), tf32r(v.w));
}
__global__ void bcat_kernel(const float* __restrict__ Bm) {
    int idx = blockIdx.x * blockDim.x + threadIdx.x;
    if (idx < ODIM * ERD) {
        int o  = idx >> 7;
        int er = idx & 127;
        int e = er >> 4, r = er & 15;
        ((uint32_t*)g_BcatT)[idx] = tf32r(Bm[((size_t)e * ODIM + o) * RRNK + r]);
    }
}

// ---------------------------------------------------------------------------
// Exact fp32 router logits
// ---------------------------------------------------------------------------
__global__ __launch_bounds__(256, 1)
void logits_kernel(const float* __restrict__ x, const float* __restrict__ rW) {
    int tid = threadIdx.x;
    int tok = blockIdx.x * 64 + (tid >> 2);
    int part = tid & 3;
    u64 acc[NLOG];
#pragma unroll
    for (int n = 0; n < NLOG; n++) acc[n] = 0;
    const float4* xr = (const float4*)(x + (size_t)tok * DDIM);
    for (int k4 = part; k4 < DDIM / 4; k4 += 4) {
        float4 xv = xr[k4];
        u64 xp0 = pack2(xv.x, xv.y), xp1 = pack2(xv.z, xv.w);
#pragma unroll
        for (int n = 0; n < NLOG; n++) {
            float4 wv = ((const float4*)(rW + (size_t)n * DDIM))[k4];
            fma2(acc[n], xp0, pack2(wv.x, wv.y));
            fma2(acc[n], xp1, pack2(wv.z, wv.w));
        }
    }
    __shared__ float red[4][64][NLOG + 1];
#pragma unroll
    for (int n = 0; n < NLOG; n++) {
        float lo, hi; unpack2(acc[n], lo, hi);
        red[part][tid >> 2][n] = lo + hi;
    }
    __syncthreads();
    if (part == 0) {
        int tl = tid >> 2;
#pragma unroll
        for (int n = 0; n < NLOG; n++)
            g_h[(size_t)tok * 192 + ERD + n] =
                red[0][tl][n] + red[1][tl][n] + red[2][tl][n] + red[3][tl][n];
    }
}

// ---------------------------------------------------------------------------
// h GEMM (tf32 mma):  g_h[:, 0:128] = g_xr @ g_ar^T
// ---------------------------------------------------------------------------
#define BMH 64
#define BNH 128
#define AH_BYTES (BMH * 32 * 4)           // 8192
#define BH_BYTES (BNH * 32 * 4)           // 16384
#define STGH_BYTES (AH_BYTES + BH_BYTES)  // 24576
#define SMEMH_BYTES (3 * STGH_BYTES)      // 73728

__device__ __forceinline__ void hwr_issue(int i, int stg, int m0, int tid,
                                          uint32_t smem_base) {
    int k0 = i * 32;
    uint32_t sa = smem_base + stg * STGH_BYTES;
    uint32_t sb = sa + AH_BYTES;
#pragma unroll
    for (int j = 0; j < 2; j++) {
        int g = tid + j * 256, row = g >> 3, u = g & 7;
        cpasync16(sa + row * 128 + ((u ^ PERM(row)) << 4),
                  g_xr + (size_t)(m0 + row) * DDIM + k0 + u * 4);
    }
#pragma unroll
    for (int j = 0; j < 4; j++) {
        int g = tid + j * 256, row = g >> 3, u = g & 7;
        cpasync16(sb + row * 128 + ((u ^ PERM(row)) << 4),
                  g_ar + (size_t)row * DDIM + k0 + u * 4);
    }
}

__global__ __launch_bounds__(256, 1)
void hwr_kernel() {
    extern __shared__ char smem[];
    uint32_t smem_base = smem_u32(smem);
    int tid = threadIdx.x;
    int wid = tid >> 5;
    int lane = tid & 31;
    int wm = wid >> 2;
    int wn = wid & 3;
    int c = lane & 3;
    int rq = lane >> 2;
    int m0 = blockIdx.x * BMH;

    float acc[2][4][4];
#pragma unroll
    for (int i = 0; i < 2; i++)
#pragma unroll
        for (int j = 0; j < 4; j++)
#pragma unroll
            for (int q = 0; q < 4; q++) acc[i][j][q] = 0.f;

    int aoff[2][2], boff[4];
#pragma unroll
    for (int i = 0; i < 2; i++) {
        int r0 = wm * 32 + i * 16 + rq, r1 = r0 + 8;
        aoff[i][0] = r0 * 128 + ((c ^ PERM(r0)) << 4);
        aoff[i][1] = r1 * 128 + ((c ^ PERM(r1)) << 4);
    }
#pragma unroll
    for (int j = 0; j < 4; j++) {
        int n = wn * 32 + j * 8 + rq;
        boff[j] = n * 128 + ((c ^ PERM(n)) << 4);
    }

    hwr_issue(0, 0, m0, tid, smem_base);
    asm volatile("cp.async.commit_group;" ::: "memory");
    hwr_issue(1, 1, m0, tid, smem_base);
    asm volatile("cp.async.commit_group;" ::: "memory");

    const int NCH = DDIM / 32;
    for (int i = 0; i < NCH; i++) {
        asm volatile("cp.async.wait_group 1;" ::: "memory");
        __syncthreads();
        if (i + 2 < NCH) hwr_issue(i + 2, (i + 2) % 3, m0, tid, smem_base);
        asm volatile("cp.async.commit_group;" ::: "memory");

        const char* sa = smem + (i % 3) * STGH_BYTES;
        const char* sb = sa + AH_BYTES;
#pragma unroll
        for (int p = 0; p < 2; p++) {
            uint4 af[2][2], bf[4];
#pragma unroll
            for (int ii = 0; ii < 2; ii++) {
                af[ii][0] = *(const uint4*)(sa + (aoff[ii][0] ^ (p << 6)));
                af[ii][1] = *(const uint4*)(sa + (aoff[ii][1] ^ (p << 6)));
            }
#pragma unroll
            for (int jj = 0; jj < 4; jj++)
                bf[jj] = *(const uint4*)(sb + (boff[jj] ^ (p << 6)));
#pragma unroll
            for (int ii = 0; ii < 2; ii++)
#pragma unroll
                for (int jj = 0; jj < 4; jj++) {
                    mma_tf32(acc[ii][jj],
                             af[ii][0].x, af[ii][1].x, af[ii][0].y, af[ii][1].y,
                             bf[jj].x, bf[jj].y);
                    mma_tf32(acc[ii][jj],
                             af[ii][0].z, af[ii][1].z, af[ii][0].w, af[ii][1].w,
                             bf[jj].z, bf[jj].w);
                }
        }
    }

#pragma unroll
    for (int j = 0; j < 4; j++) {
        int col = wn * 32 + j * 8 + 2 * c;
#pragma unroll
        for (int i = 0; i < 2; i++) {
            int row = m0 + wm * 32 + i * 16 + rq;
            *(float2*)(g_h + (size_t)row * 192 + col) =
                make_float2(acc[i][j][0], acc[i][j][1]);
            *(float2*)(g_h + (size_t)(row + 8) * 192 + col) =
                make_float2(acc[i][j][2], acc[i][j][3]);
        }
    }
}

// ---------------------------------------------------------------------------
// w_kernel + scale_kernel
// ---------------------------------------------------------------------------
__global__ void w_kernel(const float* __restrict__ rb,
                         const int* __restrict__ emap) {
    int t = blockIdx.x * blockDim.x + threadIdx.x;
    if (t >= MTOK) return;
    float p[NLOG];
    float mx = -1e30f;
#pragma unroll
    for (int n = 0; n < NLOG; n++) {
        p[n] = g_h[(size_t)t * 192 + ERD + n] + rb[n];
        mx = fmaxf(mx, p[n]);
    }
    float s = 0.f;
#pragma unroll
    for (int n = 0; n < NLOG; n++) { p[n] = expf(p[n] - mx); s += p[n]; }
    float inv = 1.f / s;
#pragma unroll
    for (int n = 0; n < NLOG; n++) p[n] *= inv;
    float wacc[NEXP];
#pragma unroll
    for (int e = 0; e < NEXP; e++) wacc[e] = 0.f;
    bool used[NLOG];
#pragma unroll
    for (int n = 0; n < NLOG; n++) used[n] = false;
    for (int k = 0; k < NEXP; k++) {
        int best = 0; float bv = -1e30f;
        for (int n = 0; n < NLOG; n++)
            if (!used[n] && p[n] > bv) { bv = p[n]; best = n; }
        used[best] = true;
        wacc[emap[best]] += bv;
    }
#pragma unroll
    for (int e = 0; e < NEXP; e++) g_w[t * NEXP + e] = wacc[e];
}

__global__ void scale_kernel() {
    int idx = blockIdx.x * blockDim.x + threadIdx.x;
    int t = idx >> 5;
    int er4 = (idx & 31) * 4;
    float wv = g_w[t * NEXP + (er4 >> 4)] * SCALING;
    const float* h = g_h + (size_t)t * 192 + er4;
    ((uint4*)(g_hw + (size_t)t * ERD + er4))[0] =
        make_uint4(tf32r(h[0] * wv), tf32r(h[1] * wv),
                   tf32r(h[2] * wv), tf32r(h[3] * wv));
}

// ---------------------------------------------------------------------------
// Main GEMM: tf32 mma.sync, KC=64 chunks (2x fewer syncs), 2-stage cp.async.
//   out = x@W^T (K=4096) + hw@BcatT^T (K=128) + bias
// CTA 128x256, 8 warps (2x4), warp tile 64x64.
// Each 64-k chunk = two consecutive 32-k sub-blocks, each with the same
// conflict-free PERM layout as before (128B rows, 16B unit u at u^PERM(row)).
// ---------------------------------------------------------------------------
#define BM 128
#define BN 256
#define KC 64
#define NCH_BASE (DDIM / KC)             // 64
#define NCHUNK   (NCH_BASE + ERD / KC)   // 66
#define NSTAGE 2
#define ASUB_BYTES (BM * 32 * 4)         // 16384  (per 32-k sub-block)
#define BSUB_BYTES (BN * 32 * 4)         // 32768
#define A_BYTES (2 * ASUB_BYTES)         // 32768
#define B_BYTES (2 * BSUB_BYTES)         // 65536
#define STG_BYTES (A_BYTES + B_BYTES)    // 98304
#define SMEM_BYTES (NSTAGE * STG_BYTES)  // 196608

__device__ __forceinline__ void issue_chunk(int i, int stg, int m0, int n0,
                                            int tid, uint32_t smem_base) {
    const float* as; const float* bs; int lda, ldb;
    if (i < NCH_BASE) {
        int k0 = i * KC; as = g_xr + k0; lda = DDIM; bs = g_wr + k0; ldb = DDIM;
    } else {
        int k0 = (i - NCH_BASE) * KC; as = g_hw + k0; lda = ERD; bs = g_BcatT + k0; ldb = ERD;
    }
    uint32_t sa = smem_base + stg * STG_BYTES;
    uint32_t sb = sa + A_BYTES;
#pragma unroll
    for (int kk = 0; kk < 2; kk++) {
#pragma unroll
        for (int j = 0; j < 4; j++) {
            int g = tid + j * 256, row = g >> 3, u = g & 7;
            cpasync16(sa + kk * ASUB_BYTES + row * 128 + ((u ^ PERM(row)) << 4),
                      as + (size_t)(m0 + row) * lda + kk * 32 + u * 4);
        }
#pragma unroll
        for (int j = 0; j < 8; j++) {
            int g = tid + j * 256, row = g >> 3, u = g & 7;
            cpasync16(sb + kk * BSUB_BYTES + row * 128 + ((u ^ PERM(row)) << 4),
                      bs + (size_t)(n0 + row) * ldb + kk * 32 + u * 4);
        }
    }
}

__global__ __launch_bounds__(256, 1)
void main_kernel(const float* __restrict__ bias, float* __restrict__ out) {
    extern __shared__ char smem[];
    uint32_t smem_base = smem_u32(smem);
    int tid = threadIdx.x;
    int wid = tid >> 5;
    int lane = tid & 31;
    int wm = wid >> 2;          // 0..1 -> rows wm*64
    int wn = wid & 3;           // 0..3 -> cols wn*64
    int c = lane & 3;
    int rq = lane >> 2;
    int m0 = blockIdx.y * BM;
    int n0 = blockIdx.x * BN;

    float acc[4][8][4];
#pragma unroll
    for (int i = 0; i < 4; i++)
#pragma unroll
        for (int j = 0; j < 8; j++)
#pragma unroll
            for (int q = 0; q < 4; q++) acc[i][j][q] = 0.f;

    int aoff[4][2], boff[8];
#pragma unroll
    for (int i = 0; i < 4; i++) {
        int r0 = wm * 64 + i * 16 + rq, r1 = r0 + 8;
        aoff[i][0] = r0 * 128 + ((c ^ PERM(r0)) << 4);
        aoff[i][1] = r1 * 128 + ((c ^ PERM(r1)) << 4);
    }
#pragma unroll
    for (int j = 0; j < 8; j++) {
        int n = wn * 64 + j * 8 + rq;
        boff[j] = n * 128 + ((c ^ PERM(n)) << 4);
    }

    issue_chunk(0, 0, m0, n0, tid, smem_base);
    asm volatile("cp.async.commit_group;" ::: "memory");

    for (int i = 0; i < NCHUNK; i++) {
        asm volatile("cp.async.wait_group 0;" ::: "memory");
        __syncthreads();
        if (i + 1 < NCHUNK)
            issue_chunk(i + 1, (i + 1) & 1, m0, n0, tid, smem_base);
        asm volatile("cp.async.commit_group;" ::: "memory");

        const char* stage = smem + (i & 1) * STG_BYTES;
#pragma unroll
        for (int kk = 0; kk < 2; kk++) {
            const char* sa = stage + kk * ASUB_BYTES;
            const char* sb = stage + A_BYTES + kk * BSUB_BYTES;
#pragma unroll
            for (int p = 0; p < 2; p++) {
                uint4 af[4][2], bf[8];
#pragma unroll
                for (int ii = 0; ii < 4; ii++) {
                    af[ii][0] = *(const uint4*)(sa + (aoff[ii][0] ^ (p << 6)));
                    af[ii][1] = *(const uint4*)(sa + (aoff[ii][1] ^ (p << 6)));
                }
#pragma unroll
                for (int jj = 0; jj < 8; jj++)
                    bf[jj] = *(const uint4*)(sb + (boff[jj] ^ (p << 6)));
#pragma unroll
                for (int ii = 0; ii < 4; ii++)
#pragma unroll
                    for (int jj = 0; jj < 8; jj++) {
                        mma_tf32(acc[ii][jj],
                                 af[ii][0].x, af[ii][1].x, af[ii][0].y, af[ii][1].y,
                                 bf[jj].x, bf[jj].y);
                        mma_tf32(acc[ii][jj],
                                 af[ii][0].z, af[ii][1].z, af[ii][0].w, af[ii][1].w,
                                 bf[jj].z, bf[jj].w);
                    }
            }
        }
    }

#pragma unroll
    for (int j = 0; j < 8; j++) {
        int col = n0 + wn * 64 + j * 8 + 2 * c;
        float2 bb = *(const float2*)(bias + col);
#pragma unroll
        for (int i = 0; i < 4; i++) {
            int row = m0 + wm * 64 + i * 16 + rq;
            float2 lo = make_float2(acc[i][j][0] + bb.x, acc[i][j][1] + bb.y);
            float2 hi = make_float2(acc[i][j][2] + bb.x, acc[i][j][3] + bb.y);
            *(float2*)(out + (size_t)row * ODIM + col) = lo;
            *(float2*)(out + (size_t)(row + 8) * ODIM + col) = hi;
        }
    }
}

extern "C" void kernel_launch(void* const* d_in, const int* in_sizes, int n_in,
                              void* d_out, int out_size) {
    const float* x    = (const float*)d_in[0];
    const float* bW   = (const float*)d_in[1];
    const float* bb   = (const float*)d_in[2];
    const float* rW   = (const float*)d_in[3];
    const float* rb   = (const float*)d_in[4];
    const float* A    = (const float*)d_in[5];
    const float* Bm   = (const float*)d_in[6];
    const int*   emap = (const int*)d_in[7];
    float* out = (float*)d_out;

    static int configured = 0;
    if (!configured) {
        cudaFuncSetAttribute(main_kernel, cudaFuncAttributeMaxDynamicSharedMemorySize,
                             SMEM_BYTES);
        cudaFuncSetAttribute(hwr_kernel, cudaFuncAttributeMaxDynamicSharedMemorySize,
                             SMEMH_BYTES);
        configured = 1;
    }

    round_x_kernel<<<(MTOK * DDIM / 4) / 256, 256>>>(x);
    round_w_kernel<<<(ODIM * DDIM / 4) / 256, 256>>>(bW);
    ar_fill_kernel<<<(ERD * DDIM / 4) / 256, 256>>>(A);
    bcat_kernel<<<(ODIM * ERD + 255) / 256, 256>>>(Bm);
    logits_kernel<<<MTOK / 64, 256>>>(x, rW);
    hwr_kernel<<<MTOK / BMH, 256, SMEMH_BYTES>>>();
    w_kernel<<<MTOK / 256, 256>>>(rb, emap);
    scale_kernel<<<(MTOK * ERD / 4) / 256, 256>>>();
    dim3 grid(ODIM / BN, MTOK / BM);
    main_kernel<<<grid, 256, SMEM_BYTES>>>(bb, out);
}